// round 17
// baseline (speedup 1.0000x reference)
#include <cuda_runtime.h>

// ---------------------------------------------------------------------------
// DNN_KalmanNet_SLAM — fused, barrier-free (NaN-sentinel dataflow), R17:
// l1's W1 reads converted from scattered per-row scalar LDGs (196 L1tex
// wavefronts/warp) to warp-local coalesced float4 staging (~16 wavefronts),
// computed from smem scratch. Scratch is a union later reused by the head
// block for its W2a/W2b prefetch (after the s_l1 sync).
// ---------------------------------------------------------------------------

#define NB     10
#define NT     512
#define WPB    16
#define H1     560
#define GH     145
#define HEADB  (NB - 1)

#define QNAN 0x7fc00000u
#define N1  QNAN
#define N2  N1, N1
#define N4  N2, N2
#define N8  N4, N4
#define N16 N8, N8
#define N64 N16, N16, N16, N16
#define N128 N64, N64
__device__ unsigned g_h0_bits[GH] = { N128, N16, N1 };
__device__ unsigned g_h1_bits[GH] = { N128, N16, N1 };

__device__ __forceinline__ float wsum(float v) {
#pragma unroll
    for (int o = 16; o; o >>= 1) v += __shfl_down_sync(0xffffffffu, v, o);
    return v;
}
__device__ __forceinline__ float sigm(float x) { return 1.0f / (1.0f + __expf(-x)); }
__device__ __forceinline__ float tanha(float x) {
    float y; asm("tanh.approx.f32 %0, %1;" : "=f"(y) : "f"(x)); return y;
}

__global__ __launch_bounds__(NT, 1)
void kalmannet_kernel(
    const float* __restrict__ state_inno, const float* __restrict__ obs_inno,
    const float* __restrict__ diff_state, const float* __restrict__ diff_obs,
    const float* __restrict__ W1,   const float* __restrict__ b1,
    const float* __restrict__ Wih0, const float* __restrict__ Whh0,
    const float* __restrict__ bih0, const float* __restrict__ bhh0,
    const float* __restrict__ Wih1, const float* __restrict__ Whh1,
    const float* __restrict__ bih1, const float* __restrict__ bhh1,
    const float* __restrict__ W2a,  const float* __restrict__ b2a,
    const float* __restrict__ W2b,  const float* __restrict__ b2b,
    const float* __restrict__ hn,
    float* __restrict__ out)
{
    __shared__ __align__(16) float s_l1[H1];
    __shared__ float s_x[16];
    __shared__ float s_hn[2 * GH];
    __shared__ float s_v[GH + 8];
    __shared__ float s_hid[40];
    __shared__ float s_b2a[40];
    __shared__ float s_b2b[10];
    // Scratch union: [stage A] 18 warp-slices of 448 floats (W1 rows staging)
    //                [post-l1, head block] W2a (5800) + W2b (400)
    __shared__ __align__(16) float s_u[18 * 448];   // 8064 floats = 32.25 KB
    float* s_w2a = s_u;            // 5800 floats
    float* s_w2b = s_u + 5800;     // 400 floats

    const int t    = threadIdx.x;
    const int lane = t & 31;
    const int lw   = t >> 5;
    const int e    = blockIdx.x * WPB + lw;
    const bool act = (e < GH);

    // ---- inputs ----
    if (t < 14) {
        float v;
        if      (t < 5)  v = state_inno[t];
        else if (t < 7)  v = obs_inno[t - 5];
        else if (t < 12) v = diff_state[t - 7];
        else             v = diff_obs[t - 12];
        s_x[t] = v;
    }
    for (int i = t; i < 2 * GH; i += NT) s_hn[i] = __ldg(hn + i);

    // ---- stage W1 rows coalesced into warp-local scratch (float4) ----
    // Warp w owns rows [32w, 32w+32): 112 float4 at global f4 index w*112.
    // Warps 0,1 additionally stage rows [512,544) / [544,560) into slices 16,17.
    {
        const float4* w1v = (const float4*)W1;          // 1960 float4 total
        float4* dst = (float4*)(s_u + lw * 448);
#pragma unroll
        for (int i = lane; i < 112; i += 32)
            dst[i] = __ldg(w1v + lw * 112 + i);
        if (lw < 2) {
            float4* dst2 = (float4*)(s_u + (16 + lw) * 448);
            int cnt = (lw == 0) ? 112 : 56;             // rows 512-543 / 544-559
            for (int i = lane; i < cnt; i += 32)
                dst2[i] = __ldg(w1v + 1792 + lw * 112 + i);
        }
    }

    // ---- prefetch Wih1 rows into registers (independent of h0) ----
    float w1r[5], w1z[5], w1n[5];
    if (act) {
        const float* pr = Wih1 + e * GH;
        const float* pz = Wih1 + (e + GH) * GH;
        const float* pn = Wih1 + (e + 2 * GH) * GH;
#pragma unroll
        for (int i = 0; i < 5; i++) {
            int k = lane + 32 * i;
            bool ok = (k < GH);
            w1r[i] = ok ? __ldg(pr + k) : 0.f;
            w1z[i] = ok ? __ldg(pz + k) : 0.f;
            w1n[i] = ok ? __ldg(pn + k) : 0.f;
        }
    }
    __syncthreads();   // s_x, s_hn, all scratch slices ready

    // ---- l1 from warp-local scratch (2-way-conflict LDS, cheap) ----
    {
        int r = 32 * lw + lane;                          // rows 0..511
        const float* wrow = s_u + lw * 448 + lane * 14;
        float s = b1[r];
#pragma unroll
        for (int k = 0; k < 14; k++) s = fmaf(wrow[k], s_x[k], s);
        s_l1[r] = fmaxf(s, 0.0f);
        if (lw < 2) {
            int r2 = 512 + 32 * lw + lane;               // rows 512..559
            if (r2 < H1) {
                const float* wrow2 = s_u + (16 + lw) * 448 + lane * 14;
                float s2 = b1[r2];
#pragma unroll
                for (int k = 0; k < 14; k++) s2 = fmaf(wrow2[k], s_x[k], s2);
                s_l1[r2] = fmaxf(s2, 0.0f);
            }
        }
    }

    // ---- recurrent dots for BOTH layers (coalesced rows, reg results) ----
    float A0 = 0.f, A1 = 0.f, A2 = 0.f;
    float B0 = 0.f, B1 = 0.f, B2 = 0.f;
    float bi0r = 0.f, bi0z = 0.f, bi0n = 0.f;
    float bi1r = 0.f, bi1z = 0.f, bi1n = 0.f;
    if (act) {
        const float* q0r = Whh0 + e * GH;
        const float* q0z = Whh0 + (e + GH) * GH;
        const float* q0n = Whh0 + (e + 2 * GH) * GH;
        const float* q1r = Whh1 + e * GH;
        const float* q1z = Whh1 + (e + GH) * GH;
        const float* q1n = Whh1 + (e + 2 * GH) * GH;
#pragma unroll 5
        for (int k = lane; k < GH; k += 32) {
            float h0v = s_hn[k], h1v = s_hn[GH + k];
            A0 = fmaf(q0r[k], h0v, A0);
            A1 = fmaf(q0z[k], h0v, A1);
            A2 = fmaf(q0n[k], h0v, A2);
            B0 = fmaf(q1r[k], h1v, B0);
            B1 = fmaf(q1z[k], h1v, B1);
            B2 = fmaf(q1n[k], h1v, B2);
        }
        A0 = wsum(A0); A1 = wsum(A1); A2 = wsum(A2);
        B0 = wsum(B0); B1 = wsum(B1); B2 = wsum(B2);
        if (lane == 0) {
            A0 += bhh0[e];  A1 += bhh0[e + GH];  A2 += bhh0[e + 2 * GH];
            B0 += bhh1[e];  B1 += bhh1[e + GH];  B2 += bhh1[e + 2 * GH];
            bi0r = bih0[e]; bi0z = bih0[e + GH]; bi0n = bih0[e + 2 * GH];
            bi1r = bih1[e]; bi1z = bih1[e + GH]; bi1n = bih1[e + 2 * GH];
        }
    }
    __syncthreads();   // s_l1 final; scratch free for reuse

    // ---- head block: idle warps now prefetch head weights into scratch ----
    if (blockIdx.x == HEADB && lw >= 1) {
        for (int i = t - 32; i < 40 * GH; i += NT - 32) s_w2a[i] = W2a[i];
        if (lw == 1) {
            if (lane < 10) s_b2b[lane] = b2b[lane];
            for (int i = lane; i < 40; i += 32) s_b2a[i] = b2a[i];
        }
        if (lw >= 2) {
            for (int i = t - 64; i < 400; i += NT - 64) s_w2b[i] = W2b[i];
        }
    }

    // ---- GRU layer 0: Wih0 @ l1 (float4), publish h0 (store==signal) ----
    if (act) {
        const float4* xr = (const float4*)s_l1;
        const float4* wr = (const float4*)(Wih0 + e * H1);
        const float4* wz = (const float4*)(Wih0 + (e + GH) * H1);
        const float4* wn = (const float4*)(Wih0 + (e + 2 * GH) * H1);
        float sr = 0.f, sz = 0.f, sn = 0.f;
#pragma unroll
        for (int i = 0; i < 5; i++) {
            int k = lane + 32 * i;
            if (k < H1 / 4) {
                float4 x = xr[k];
                float4 a = wr[k];
                sr += a.x * x.x + a.y * x.y + a.z * x.z + a.w * x.w;
                float4 b = wz[k];
                sz += b.x * x.x + b.y * x.y + b.z * x.z + b.w * x.w;
                float4 c = wn[k];
                sn += c.x * x.x + c.y * x.y + c.z * x.z + c.w * x.w;
            }
        }
        sr = wsum(sr); sz = wsum(sz); sn = wsum(sn);
        if (lane == 0) {
            float r = sigm(sr + bi0r + A0);
            float z = sigm(sz + bi0z + A1);
            float n = tanha(sn + bi0n + r * A2);
            float h0 = (1.0f - z) * n + z * s_hn[e];
            ((volatile unsigned*)g_h0_bits)[e] = __float_as_uint(h0);
        }
    }

    // ---- GRU layer 1: poll g_h0 (data==signal), reg weights ----
    if (act) {
        unsigned b[5];
#pragma unroll
        for (int i = 0; i < 5; i++) b[i] = (lane + 32 * i < GH) ? QNAN : 0u;
        volatile unsigned* p = (volatile unsigned*)g_h0_bits;
        for (;;) {
            bool all = true;
#pragma unroll
            for (int i = 0; i < 5; i++) {
                int k = lane + 32 * i;
                if (k < GH && b[i] == QNAN) {
                    b[i] = p[k];
                    if (b[i] == QNAN) all = false;
                }
            }
            if (__all_sync(0xffffffffu, all)) break;
        }
        float sr = 0.f, sz = 0.f, sn = 0.f;
#pragma unroll
        for (int i = 0; i < 5; i++) {
            float x = __uint_as_float(b[i]);
            if (lane + 32 * i >= GH) x = 0.f;
            sr = fmaf(w1r[i], x, sr);
            sz = fmaf(w1z[i], x, sz);
            sn = fmaf(w1n[i], x, sn);
        }
        sr = wsum(sr); sz = wsum(sz); sn = wsum(sn);
        if (lane == 0) {
            float r = sigm(sr + bi1r + B0);
            float z = sigm(sz + bi1z + B1);
            float n = tanha(sn + bi1n + r * B2);
            float h1 = (1.0f - z) * n + z * s_hn[GH + e];
            ((volatile unsigned*)g_h1_bits)[e] = __float_as_uint(h1);
        }
    }

    // ---- non-head blocks are done ----
    if (blockIdx.x != HEADB) return;

    // ---- head: poll all h1 into smem ----
    if (t < GH) {
        volatile unsigned* p = (volatile unsigned*)g_h1_bits;
        unsigned v;
        do { v = p[t]; } while (v == QNAN);
        s_v[t] = __uint_as_float(v);
    }
    __syncthreads();

    // ---- output head (weights in scratch smem; 16 warps) ----
    for (int r = lw; r < 40; r += WPB) {
        const float* w = &s_w2a[r * GH];
        float s = 0.f;
#pragma unroll 5
        for (int k = lane; k < GH; k += 32) s = fmaf(w[k], s_v[k], s);
        s = wsum(s);
        if (lane == 0) s_hid[r] = fmaxf(s + s_b2a[r], 0.0f);
    }
    __syncthreads();
    if (t < 10) {
        const float* w = &s_w2b[t * 40];
        float s = s_b2b[t];
#pragma unroll
        for (int k = 0; k < 40; k++) s = fmaf(w[k], s_hid[k], s);
        out[t] = s;
    }

    // ---- reset sentinels for next graph replay ----
    for (int i = t; i < GH; i += NT) {
        g_h0_bits[i] = QNAN;
        g_h1_bits[i] = QNAN;
    }
}

extern "C" void kernel_launch(void* const* d_in, const int* in_sizes, int n_in,
                              void* d_out, int out_size) {
    (void)in_sizes; (void)n_in; (void)out_size;
    kalmannet_kernel<<<NB, NT>>>(
        (const float*)d_in[0],  (const float*)d_in[1],
        (const float*)d_in[2],  (const float*)d_in[3],
        (const float*)d_in[4],  (const float*)d_in[5],
        (const float*)d_in[6],  (const float*)d_in[7],
        (const float*)d_in[8],  (const float*)d_in[9],
        (const float*)d_in[10], (const float*)d_in[11],
        (const float*)d_in[12], (const float*)d_in[13],
        (const float*)d_in[14], (const float*)d_in[15],
        (const float*)d_in[16], (const float*)d_in[17],
        (const float*)d_in[18],
        (float*)d_out);
}